// round 13
// baseline (speedup 1.0000x reference)
#include <cuda_runtime.h>
#include <cuda_fp16.h>
#include <cstdint>

#define T_STEPS 128
#define BATCH   512
#define NLAB    512
#define HID     1024
#define SEM     1024
#define MROWS   (T_STEPS*BATCH)    // 65536
#define FIXCAP  (1u<<21)
#define GUARD   2.5e-3f

typedef unsigned long long ull;

// ---------------- scratch (device globals; no allocs allowed) ----------------
// M index is b*128 + t (batch-major): one 128-row GEMM tile = full time
// trajectory of one batch row -> LIF fuses into the epilogue.
__device__ __half g_a1  [(size_t)MROWS * NLAB];   //  64 MB spikes fp16 (b,t)-major
__device__ __half g_spk1[(size_t)MROWS * HID];    // 128 MB layer-1 spikes fp16
__device__ __half g_wh1 [(size_t)HID * NLAB];     //   1 MB W1 fp16
__device__ __half g_wh2 [(size_t)SEM * HID];      //   2 MB W2 fp16
__device__ unsigned int g_fixcnt1, g_fixcnt2;
__device__ unsigned int g_fixlist1[FIXCAP];
__device__ unsigned int g_fixlist2[FIXCAP];

// ============================================================================
// HMMA fp16 single-pass GEMM, BM=128 x BN=256, BK=64, 512 threads (16 warps,
// 4m x 4n), 2-stage cp.async pipeline, fused guarded LIF epilogue.
// fp16 weight error <= 2^-12|w|; guard+fix absorbs it exactly.
// ============================================================================
#define BM2 128
#define BN2 256
#define BK2 64
#define NTHREADS 512
#define ROWB 144                       // 64 fp16 = 128B + 16B pad (ldsm clean)
#define A_BYTES  (BM2 * ROWB)          // 18432
#define B_BYTES  (BN2 * ROWB)          // 36864
#define STAGE_BYTES (A_BYTES + B_BYTES)  // 55296; 2 stages = 110592
#define SMEM_BYTES  132096             // LIF staging 256*129*4 dominates
#define PITCH 129

__device__ __forceinline__ uint32_t s2u(const void* p) {
    uint32_t a;
    asm("{ .reg .u64 t; cvta.to.shared.u64 t, %1; cvt.u32.u64 %0, t; }" : "=r"(a) : "l"(p));
    return a;
}
__device__ __forceinline__ void cpa16(uint32_t dst, const void* src) {
    asm volatile("cp.async.cg.shared.global [%0], [%1], 16;" :: "r"(dst), "l"(src) : "memory");
}
__device__ __forceinline__ void ldsm_x4(uint32_t* r, uint32_t addr) {
    asm volatile("ldmatrix.sync.aligned.m8n8.x4.shared.b16 {%0,%1,%2,%3}, [%4];"
                 : "=r"(r[0]), "=r"(r[1]), "=r"(r[2]), "=r"(r[3]) : "r"(addr));
}
__device__ __forceinline__ void mma16816(float* c, const uint32_t* a, uint32_t b0, uint32_t b1) {
    asm volatile("mma.sync.aligned.m16n8k16.row.col.f32.f16.f16.f32 "
                 "{%0,%1,%2,%3}, {%4,%5,%6,%7}, {%8,%9}, {%0,%1,%2,%3};"
                 : "+f"(c[0]), "+f"(c[1]), "+f"(c[2]), "+f"(c[3])
                 : "r"(a[0]), "r"(a[1]), "r"(a[2]), "r"(a[3]), "r"(b0), "r"(b1));
}

// A rows are (b*128+t); blockIdx.y = b. Epilogue: acc -> smem [u][t] -> LIF.
// Both layers guard-flag borderline elements; WRITE_SPK also emits fp16 spikes.
template <int K, bool WRITE_SPK>
__global__ void __launch_bounds__(NTHREADS, 1)
gemm_lif(const __half* __restrict__ A,
         const __half* __restrict__ W,           // [1024][K] fp16
         __half* __restrict__ spk,               // WRITE_SPK only
         float* __restrict__ mean_out,
         unsigned int* __restrict__ fixcnt,
         unsigned int* __restrict__ fixlist)
{
    extern __shared__ char smem[];
    const uint32_t sb = s2u(smem);
    const int tid = threadIdx.x;
    const int b = blockIdx.y;
    const size_t mBase = (size_t)b * BM2;
    const size_t nBase = (size_t)blockIdx.x * BN2;
    constexpr int NC = K / BK2;

    auto load_stage = [&](int chunk, int stage) {
        const uint32_t s0 = sb + stage * STAGE_BYTES;
        const int k0 = chunk * BK2;
        // A: 128 rows x 128B (8 x 16B); 2 chunks per thread
        {
            int row = tid >> 2, kc = tid & 3;
            const char* src = (const char*)(A + (mBase + row) * (size_t)K + k0);
            cpa16(s0 + row * ROWB + kc * 16,      src + kc * 16);
            cpa16(s0 + row * ROWB + kc * 16 + 64, src + kc * 16 + 64);
        }
        // B: 256 rows x 8 chunks = 2048, 4 per thread
#pragma unroll
        for (int j = 0; j < 4; ++j) {
            int c = tid + j * NTHREADS;
            int row = c >> 3, kc = c & 7;
            cpa16(s0 + A_BYTES + row * ROWB + kc * 16,
                  (const char*)(W + (nBase + row) * (size_t)K + k0) + kc * 16);
        }
        asm volatile("cp.async.commit_group;" ::: "memory");
    };

    const int wid  = tid >> 5, lane = tid & 31;
    const int wm = (wid >> 2) * 32;       // 0/32/64/96
    const int wn = (wid & 3) * 64;        // 0/64/128/192

    float acc[2][8][4];
#pragma unroll
    for (int mi = 0; mi < 2; ++mi)
#pragma unroll
        for (int ni = 0; ni < 8; ++ni)
#pragma unroll
            for (int q = 0; q < 4; ++q) acc[mi][ni][q] = 0.f;

    load_stage(0, 0);

    const uint32_t a_lrow = (uint32_t)(lane & 15);
    const uint32_t a_koff = (uint32_t)(lane >> 4) * 8;
    const uint32_t b_lrow = (uint32_t)(((lane >> 3) & 1) * 8 + (lane & 7));
    const uint32_t b_koff = (uint32_t)(lane >> 4) * 8;

    for (int i = 0; i < NC; ++i) {
        asm volatile("cp.async.wait_group 0;" ::: "memory");
        __syncthreads();                  // stage i visible; all done with i-1
        if (i + 1 < NC) load_stage(i + 1, (i + 1) & 1);   // overlaps compute

        const uint32_t s0 = sb + (i & 1) * STAGE_BYTES;
#pragma unroll
        for (int ks = 0; ks < 4; ++ks) {
            const int k = ks * 16;
            uint32_t af[2][4];
#pragma unroll
            for (int mi = 0; mi < 2; ++mi)
                ldsm_x4(af[mi], s0 + (wm + mi * 16 + a_lrow) * ROWB + (k + a_koff) * 2);
            const uint32_t bbase = s0 + A_BYTES;
#pragma unroll
            for (int nb = 0; nb < 4; ++nb) {
                uint32_t q[4];
                ldsm_x4(q, bbase + (wn + nb * 16 + b_lrow) * ROWB + (k + b_koff) * 2);
#pragma unroll
                for (int mi = 0; mi < 2; ++mi) {
                    mma16816(acc[mi][2 * nb],     af[mi], q[0], q[2]);
                    mma16816(acc[mi][2 * nb + 1], af[mi], q[1], q[3]);
                }
            }
        }
    }

    // ---- fused guarded LIF epilogue ----
    asm volatile("cp.async.wait_group 0;" ::: "memory");
    __syncthreads();                    // all compute + loads done; reuse smem
    float* sf = (float*)smem;           // [u][t], pitch PITCH (conflict-free)
    const int r0 = lane >> 2, c0 = (lane & 3) * 2;
#pragma unroll
    for (int mi = 0; mi < 2; ++mi)
#pragma unroll
        for (int ni = 0; ni < 8; ++ni) {
            const int t0 = wm + mi * 16 + r0;
            const int u0 = wn + ni * 8 + c0;
            sf[(u0    ) * PITCH + t0    ] = acc[mi][ni][0];
            sf[(u0 + 1) * PITCH + t0    ] = acc[mi][ni][1];
            sf[(u0    ) * PITCH + t0 + 8] = acc[mi][ni][2];
            sf[(u0 + 1) * PITCH + t0 + 8] = acc[mi][ni][3];
        }
    __syncthreads();

    if (tid < BN2) {
        const int u = tid;              // one unit per thread
        const size_t uglob = nBase + u;
        float v = 0.f, cnt = 0.f;
        int bad = 0;
#pragma unroll 8
        for (int t = 0; t < T_STEPS; ++t) {
            float x = sf[u * PITCH + t];
            v = fmaf(0.95f, v, x);
            bad |= (fabsf(v - 1.0f) < GUARD);
            float s = (v > 1.0f) ? 1.0f : 0.0f;
            v *= (1.0f - s);
            cnt += s;
            if (WRITE_SPK)
                spk[(mBase + t) * 1024 + uglob] = __float2half(s);
        }
        mean_out[(size_t)b * 1024 + uglob] = cnt * (1.0f / 128.0f);
        if (bad) {
            unsigned int pos = atomicAdd(fixcnt, 1u);
            if (pos < FIXCAP) fixlist[pos] = (unsigned int)(b * 1024 + uglob);
        }
    }
}

// ============================================================================
// Exact recompute of flagged elements. One warp per element; lane owns
// timestep t = slot*32+lane, computes I via a PRIVATE ASCENDING-k fp32 FMA
// chain (bit-compatible with the R1-validated exact path). LIF via shuffle.
// ============================================================================
template <int KK, bool WRITE_SPK>
__global__ void __launch_bounds__(128)
fix_kernel(const __half* __restrict__ Ain,        // (b*128+t, KK) fp16 inputs
           const float* __restrict__ Wf,          // (1024, KK) fp32 weights
           __half* __restrict__ spk,              // layer-1 spike rewrite
           float* __restrict__ mean_out,
           const unsigned int* __restrict__ fixcnt,
           const unsigned int* __restrict__ fixlist)
{
    const unsigned int nfix = min(*fixcnt, FIXCAP);
    const int lane = threadIdx.x & 31;
    const int gw = (blockIdx.x * blockDim.x + threadIdx.x) >> 5;
    const int nw = (gridDim.x * blockDim.x) >> 5;

    for (unsigned int w = gw; w < nfix; w += nw) {
        const unsigned int idx = fixlist[w];
        const int b = idx >> 10, u = idx & 1023;
        const float* wr = Wf + (size_t)u * KK;   // lane-uniform -> broadcast

        float Iv[4];
#pragma unroll
        for (int slot = 0; slot < 4; ++slot) {
            const int t = slot * 32 + lane;
            const __half* xr = Ain + ((size_t)b * T_STEPS + t) * KK;
            float a = 0.f;
            for (int kk = 0; kk < KK; kk += 8) {        // ascending k, in order
                uint4 raw = *(const uint4*)(xr + kk);   // 8 fp16
                float4 w0 = *(const float4*)(wr + kk);
                float4 w1 = *(const float4*)(wr + kk + 4);
                const __half2* px = (const __half2*)&raw;
                a = fmaf(__half2float(px[0].x), w0.x, a);
                a = fmaf(__half2float(px[0].y), w0.y, a);
                a = fmaf(__half2float(px[1].x), w0.z, a);
                a = fmaf(__half2float(px[1].y), w0.w, a);
                a = fmaf(__half2float(px[2].x), w1.x, a);
                a = fmaf(__half2float(px[2].y), w1.y, a);
                a = fmaf(__half2float(px[3].x), w1.z, a);
                a = fmaf(__half2float(px[3].y), w1.w, a);
            }
            Iv[slot] = a;
        }
        float v = 0.f, cnt = 0.f;
        for (int t = 0; t < T_STEPS; ++t) {
            float x = __shfl_sync(0xffffffffu, Iv[t >> 5], t & 31);
            v = fmaf(0.95f, v, x);
            float s = (v > 1.0f) ? 1.0f : 0.0f;
            v *= (1.0f - s);
            cnt += s;
            if (WRITE_SPK && lane == 0)
                spk[((size_t)b * T_STEPS + t) * 1024 + u] = __float2half(s);
        }
        if (lane == 0) mean_out[idx] = cnt * (1.0f / 128.0f);
    }
}

// ============================================================================
// prep kernels
// ============================================================================
__global__ void zero_cnt_kernel()
{
    if (threadIdx.x == 0) { g_fixcnt1 = 0; g_fixcnt2 = 0; }
}

// transpose (t,b) -> (b,t) rows while converting fp32 -> fp16 (binary: exact)
__global__ void __launch_bounds__(128)
f2h_t_kernel(const float* __restrict__ x, __half* __restrict__ y)
{
    const int row = blockIdx.x;            // t*BATCH + b
    const int t = row >> 9, b = row & 511;
    const float4* src = (const float4*)(x + (size_t)row * NLAB);
    __half* dst = y + ((size_t)b * T_STEPS + t) * NLAB;
    float4 v = src[threadIdx.x];
    __half2 a; a.x = __float2half(v.x); a.y = __float2half(v.y);
    __half2 c; c.x = __float2half(v.z); c.y = __float2half(v.w);
    *(__half2*)(dst + threadIdx.x * 4)     = a;
    *(__half2*)(dst + threadIdx.x * 4 + 2) = c;
}

// fp16 weight snapshot: error <= 2^-12 |w| (guard+fix absorbs)
__global__ void __launch_bounds__(256)
wh_kernel(const float* __restrict__ w, __half* __restrict__ o, int n)
{
    int i = blockIdx.x * blockDim.x + threadIdx.x;
    if (i >= n) return;
    o[i] = __float2half_rn(w[i]);
}

// ---------------------------------------------------------------------------
extern "C" void kernel_launch(void* const* d_in, const int* in_sizes, int n_in,
                              void* d_out, int out_size)
{
    const float* spikes = (const float*)d_in[0];   // (T, B, NLAB) fp32
    const float* W1     = (const float*)d_in[1];   // (HID, NLAB)
    const float* W2     = (const float*)d_in[2];   // (SEM, HID)
    float* out = (float*)d_out;                    // [mean1 | mean2]

    __half *a1, *spk1, *wh1, *wh2;
    unsigned int *fc1, *fc2, *fl1, *fl2;
    cudaGetSymbolAddress((void**)&a1,   g_a1);
    cudaGetSymbolAddress((void**)&spk1, g_spk1);
    cudaGetSymbolAddress((void**)&wh1,  g_wh1);
    cudaGetSymbolAddress((void**)&wh2,  g_wh2);
    cudaGetSymbolAddress((void**)&fc1,  g_fixcnt1);
    cudaGetSymbolAddress((void**)&fc2,  g_fixcnt2);
    cudaGetSymbolAddress((void**)&fl1,  g_fixlist1);
    cudaGetSymbolAddress((void**)&fl2,  g_fixlist2);

    cudaFuncSetAttribute((const void*)gemm_lif<512, true>,
                         cudaFuncAttributeMaxDynamicSharedMemorySize, SMEM_BYTES);
    cudaFuncSetAttribute((const void*)gemm_lif<1024, false>,
                         cudaFuncAttributeMaxDynamicSharedMemorySize, SMEM_BYTES);

    // prep
    zero_cnt_kernel<<<1, 32>>>();
    f2h_t_kernel<<<MROWS, 128>>>(spikes, a1);
    wh_kernel<<<(HID * NLAB) / 256, 256>>>(W1, wh1, HID * NLAB);
    wh_kernel<<<(SEM * HID) / 256, 256>>>(W2, wh2, SEM * HID);

    // layer 1: fp16 HMMA + fused guarded LIF, then exact-order fixup
    gemm_lif<512, true><<<dim3(HID / BN2, BATCH), NTHREADS, SMEM_BYTES>>>(
        a1, wh1, spk1, out, fc1, fl1);
    fix_kernel<512, true><<<2048, 128>>>(a1, W1, spk1, out, fc1, fl1);

    // layer 2: fp16 HMMA + fused guarded LIF, then exact-order fixup (mean only)
    gemm_lif<1024, false><<<dim3(SEM / BN2, BATCH), NTHREADS, SMEM_BYTES>>>(
        spk1, wh2, nullptr, out + (size_t)BATCH * HID, fc2, fl2);
    fix_kernel<1024, false><<<2048, 128>>>(spk1, W2, nullptr,
                                           out + (size_t)BATCH * HID, fc2, fl2);
}

// round 14
// speedup vs baseline: 3.4506x; 3.4506x over previous
#include <cuda_runtime.h>
#include <cuda_bf16.h>
#include <cstdint>

#define T_STEPS 128
#define BATCH   512
#define NLAB    512
#define HID     1024
#define SEM     1024
#define MROWS   (T_STEPS*BATCH)    // 65536
#define GUARD   5e-5f

typedef unsigned long long ull;

// ---------------- scratch (device globals; no allocs allowed) ----------------
// M index is b*128 + t (batch-major): one 128-row GEMM tile = full time
// trajectory of one batch row -> LIF fuses into the epilogue.
__device__ __nv_bfloat16 g_a1  [(size_t)MROWS * NLAB];   //  64 MB spikes bf16 (b,t)-major
__device__ __nv_bfloat16 g_spk1[(size_t)MROWS * HID];    // 128 MB layer-1 spikes bf16
__device__ __nv_bfloat16 g_ws1 [2ull * HID * NLAB];      //   2 MB W1 2-splits
__device__ __nv_bfloat16 g_ws2 [2ull * SEM * HID];       //   4 MB W2 2-splits

// ============================================================================
// HMMA 2-split GEMM, BM=128 x BN=256 tile, BK=64, 512 threads (16 warps,
// 4m x 4n), 2-stage cp.async pipeline, fused guarded LIF epilogue with
// IN-CTA exact fixup of flagged borderline elements.
// ============================================================================
#define BM2 128
#define BN2 256
#define BK2 64
#define NTHREADS 512
#define NWARPS 16
#define ROWB 144                       // 64 bf16 = 128B + 16B pad (ldsm clean)
#define A_BYTES  (BM2 * ROWB)          // 18432
#define B_SPLIT  (BN2 * ROWB)          // 36864
#define STAGE_BYTES (A_BYTES + 2 * B_SPLIT)   // 92160
#define PITCH 129
#define STAGING_BYTES (BN2 * PITCH * 4)       // 132096
#define FLAG_OFF  STAGING_BYTES               // flag counter + list after staging
#define SMEM_BYTES (2 * STAGE_BYTES)          // 184320 (> FLAG_OFF + 1040)

__device__ __forceinline__ uint32_t s2u(const void* p) {
    uint32_t a;
    asm("{ .reg .u64 t; cvta.to.shared.u64 t, %1; cvt.u32.u64 %0, t; }" : "=r"(a) : "l"(p));
    return a;
}
__device__ __forceinline__ void cpa16(uint32_t dst, const void* src) {
    asm volatile("cp.async.cg.shared.global [%0], [%1], 16;" :: "r"(dst), "l"(src) : "memory");
}
__device__ __forceinline__ void ldsm_x4(uint32_t* r, uint32_t addr) {
    asm volatile("ldmatrix.sync.aligned.m8n8.x4.shared.b16 {%0,%1,%2,%3}, [%4];"
                 : "=r"(r[0]), "=r"(r[1]), "=r"(r[2]), "=r"(r[3]) : "r"(addr));
}
__device__ __forceinline__ void mma16816(float* c, const uint32_t* a, uint32_t b0, uint32_t b1) {
    asm volatile("mma.sync.aligned.m16n8k16.row.col.f32.bf16.bf16.f32 "
                 "{%0,%1,%2,%3}, {%4,%5,%6,%7}, {%8,%9}, {%0,%1,%2,%3};"
                 : "+f"(c[0]), "+f"(c[1]), "+f"(c[2]), "+f"(c[3])
                 : "r"(a[0]), "r"(a[1]), "r"(a[2]), "r"(a[3]), "r"(b0), "r"(b1));
}

// A rows are (b*128+t); blockIdx.y = b. Epilogue: acc -> smem [u][t] -> LIF,
// flag borderline elements, exact in-CTA recompute per flag.
template <int K, bool WRITE_SPK>
__global__ void __launch_bounds__(NTHREADS, 1)
gemm_lif(const __nv_bfloat16* __restrict__ A,
         const __nv_bfloat16* __restrict__ W,    // [2][1024][K] bf16 splits
         const float* __restrict__ Wf,           // [1024][K] fp32 (exact fix)
         __nv_bfloat16* __restrict__ spk,        // WRITE_SPK only
         float* __restrict__ mean_out)
{
    extern __shared__ char smem[];
    const uint32_t sb = s2u(smem);
    const int tid = threadIdx.x;
    const int b = blockIdx.y;
    const size_t mBase = (size_t)b * BM2;
    const size_t nBase = (size_t)blockIdx.x * BN2;
    constexpr int NC = K / BK2;

    auto load_stage = [&](int chunk, int stage) {
        const uint32_t s0 = sb + stage * STAGE_BYTES;
        const int k0 = chunk * BK2;
        // A: 128 rows x 128B (8 x 16B); 2 chunks per thread
        {
            int row = tid >> 2, kc = tid & 3;
            const char* src = (const char*)(A + (mBase + row) * (size_t)K + k0);
            cpa16(s0 + row * ROWB + kc * 16,      src + kc * 16);
            cpa16(s0 + row * ROWB + kc * 16 + 64, src + kc * 16 + 64);
        }
        // B: 2 splits x 256 rows x 8 chunks = 4096, 8 per thread
#pragma unroll
        for (int j = 0; j < 8; ++j) {
            int c = tid + j * NTHREADS;
            int sp = c >> 11, rem = c & 2047;
            int row = rem >> 3, kc = rem & 7;
            cpa16(s0 + A_BYTES + sp * B_SPLIT + row * ROWB + kc * 16,
                  (const char*)(W + sp * (size_t)1024 * K + (nBase + row) * (size_t)K + k0) + kc * 16);
        }
        asm volatile("cp.async.commit_group;" ::: "memory");
    };

    const int wid  = tid >> 5, lane = tid & 31;
    const int wm = (wid >> 2) * 32;       // 0/32/64/96
    const int wn = (wid & 3) * 64;        // 0/64/128/192

    float acc[2][8][4];
#pragma unroll
    for (int mi = 0; mi < 2; ++mi)
#pragma unroll
        for (int ni = 0; ni < 8; ++ni)
#pragma unroll
            for (int q = 0; q < 4; ++q) acc[mi][ni][q] = 0.f;

    load_stage(0, 0);

    const uint32_t a_lrow = (uint32_t)(lane & 15);
    const uint32_t a_koff = (uint32_t)(lane >> 4) * 8;
    const uint32_t b_lrow = (uint32_t)(((lane >> 3) & 1) * 8 + (lane & 7));
    const uint32_t b_koff = (uint32_t)(lane >> 4) * 8;

    for (int i = 0; i < NC; ++i) {
        asm volatile("cp.async.wait_group 0;" ::: "memory");
        __syncthreads();                  // stage i visible; all done with i-1
        if (i + 1 < NC) load_stage(i + 1, (i + 1) & 1);   // overlaps compute

        const uint32_t s0 = sb + (i & 1) * STAGE_BYTES;
#pragma unroll
        for (int ks = 0; ks < 4; ++ks) {
            const int k = ks * 16;
            uint32_t af[2][4];
#pragma unroll
            for (int mi = 0; mi < 2; ++mi)
                ldsm_x4(af[mi], s0 + (wm + mi * 16 + a_lrow) * ROWB + (k + a_koff) * 2);
#pragma unroll
            for (int sp = 0; sp < 2; ++sp) {
                const uint32_t bbase = s0 + A_BYTES + sp * B_SPLIT;
#pragma unroll
                for (int nb = 0; nb < 4; ++nb) {
                    uint32_t q[4];
                    ldsm_x4(q, bbase + (wn + nb * 16 + b_lrow) * ROWB + (k + b_koff) * 2);
#pragma unroll
                    for (int mi = 0; mi < 2; ++mi) {
                        mma16816(acc[mi][2 * nb],     af[mi], q[0], q[2]);
                        mma16816(acc[mi][2 * nb + 1], af[mi], q[1], q[3]);
                    }
                }
            }
        }
    }

    // ---- fused guarded LIF epilogue ----
    asm volatile("cp.async.wait_group 0;" ::: "memory");
    __syncthreads();                    // all compute + loads done; reuse smem
    float* sf = (float*)smem;           // [u][t], pitch PITCH (conflict-free)
    unsigned int* sflagcnt = (unsigned int*)(smem + FLAG_OFF);
    unsigned int* sflaglist = sflagcnt + 1;
    if (tid == 0) *sflagcnt = 0;

    const int r0 = lane >> 2, c0 = (lane & 3) * 2;
#pragma unroll
    for (int mi = 0; mi < 2; ++mi)
#pragma unroll
        for (int ni = 0; ni < 8; ++ni) {
            const int t0 = wm + mi * 16 + r0;
            const int u0 = wn + ni * 8 + c0;
            sf[(u0    ) * PITCH + t0    ] = acc[mi][ni][0];
            sf[(u0 + 1) * PITCH + t0    ] = acc[mi][ni][1];
            sf[(u0    ) * PITCH + t0 + 8] = acc[mi][ni][2];
            sf[(u0 + 1) * PITCH + t0 + 8] = acc[mi][ni][3];
        }
    __syncthreads();

    if (tid < BN2) {
        const int u = tid;              // one unit per thread
        const size_t uglob = nBase + u;
        float v = 0.f, cnt = 0.f;
        int bad = 0;
#pragma unroll 8
        for (int t = 0; t < T_STEPS; ++t) {
            float x = sf[u * PITCH + t];
            v = fmaf(0.95f, v, x);
            bad |= (fabsf(v - 1.0f) < GUARD);
            float s = (v > 1.0f) ? 1.0f : 0.0f;
            v *= (1.0f - s);
            cnt += s;
            if (WRITE_SPK)
                spk[(mBase + t) * 1024 + uglob] = __float2bfloat16(s);
        }
        mean_out[(size_t)b * 1024 + uglob] = cnt * (1.0f / 128.0f);
        if (bad) {
            unsigned int pos = atomicAdd(sflagcnt, 1u);
            sflaglist[pos] = (unsigned int)u;
        }
    }
    __syncthreads();

    // ---- in-CTA exact fixup (rare; A rows for batch b are L2-hot) ----
    // One warp per flagged u. Lane owns t = slot*32+lane; I via PRIVATE
    // ASCENDING-k fp32 FMA chain (bit-compatible with the validated exact
    // path); LIF sequenced by shuffle. Rewrites spk rows + mean.
    const int nflag = (int)*sflagcnt;
    for (int e = wid; e < nflag; e += NWARPS) {
        const int u = (int)sflaglist[e];
        const size_t uglob = nBase + u;
        const float* wr = Wf + uglob * (size_t)K;   // lane-uniform -> broadcast

        float Iv[4];
#pragma unroll
        for (int slot = 0; slot < 4; ++slot) {
            const int t = slot * 32 + lane;
            const __nv_bfloat16* xr = A + (mBase + t) * (size_t)K;
            float a = 0.f;
            for (int kk = 0; kk < K; kk += 8) {         // ascending k, in order
                uint4 raw = *(const uint4*)(xr + kk);   // 8 bf16
                float4 w0 = *(const float4*)(wr + kk);
                float4 w1 = *(const float4*)(wr + kk + 4);
                const __nv_bfloat162* px = (const __nv_bfloat162*)&raw;
                a = fmaf(__bfloat162float(px[0].x), w0.x, a);
                a = fmaf(__bfloat162float(px[0].y), w0.y, a);
                a = fmaf(__bfloat162float(px[1].x), w0.z, a);
                a = fmaf(__bfloat162float(px[1].y), w0.w, a);
                a = fmaf(__bfloat162float(px[2].x), w1.x, a);
                a = fmaf(__bfloat162float(px[2].y), w1.y, a);
                a = fmaf(__bfloat162float(px[3].x), w1.z, a);
                a = fmaf(__bfloat162float(px[3].y), w1.w, a);
            }
            Iv[slot] = a;
        }
        float v = 0.f, cnt = 0.f;
        for (int t = 0; t < T_STEPS; ++t) {
            float x = __shfl_sync(0xffffffffu, Iv[t >> 5], t & 31);
            v = fmaf(0.95f, v, x);
            float s = (v > 1.0f) ? 1.0f : 0.0f;
            v *= (1.0f - s);
            cnt += s;
            if (WRITE_SPK && lane == 0)
                spk[(mBase + t) * 1024 + uglob] = __float2bfloat16(s);
        }
        if (lane == 0) mean_out[(size_t)b * 1024 + uglob] = cnt * (1.0f / 128.0f);
    }
}

// ============================================================================
// prep kernels
// ============================================================================
// transpose (t,b) -> (b,t) rows while converting fp32 -> bf16 (binary: exact)
__global__ void __launch_bounds__(128)
f2bf_t_kernel(const float* __restrict__ x, __nv_bfloat16* __restrict__ y)
{
    const int row = blockIdx.x;            // t*BATCH + b
    const int t = row >> 9, b = row & 511;
    const float4* src = (const float4*)(x + (size_t)row * NLAB);
    __nv_bfloat16* dst = y + ((size_t)b * T_STEPS + t) * NLAB;
    float4 v = src[threadIdx.x];
    __nv_bfloat162 a; a.x = __float2bfloat16(v.x); a.y = __float2bfloat16(v.y);
    __nv_bfloat162 c; c.x = __float2bfloat16(v.z); c.y = __float2bfloat16(v.w);
    *(__nv_bfloat162*)(dst + threadIdx.x * 4)     = a;
    *(__nv_bfloat162*)(dst + threadIdx.x * 4 + 2) = c;
}

// 2-way bf16 split for BOTH weight matrices in one launch.
// hi = bf16(w), lo = bf16(w - hi); residual ~2^-18 |w|
__global__ void __launch_bounds__(256)
wsplit2_both_kernel(const float* __restrict__ w1, __nv_bfloat16* __restrict__ o1,
                    const float* __restrict__ w2, __nv_bfloat16* __restrict__ o2)
{
    int i = blockIdx.x * blockDim.x + threadIdx.x;
    const int n1 = HID * NLAB;             // 524288
    const int n2 = SEM * HID;              // 1048576
    if (i < n1) {
        float x = w1[i];
        __nv_bfloat16 h = __float2bfloat16(x);
        o1[i] = h; o1[n1 + i] = __float2bfloat16(x - __bfloat162float(h));
    }
    i -= n1;
    if (i >= 0 && i < n2) {
        float x = w2[i];
        __nv_bfloat16 h = __float2bfloat16(x);
        o2[i] = h; o2[n2 + i] = __float2bfloat16(x - __bfloat162float(h));
    }
}

// ---------------------------------------------------------------------------
extern "C" void kernel_launch(void* const* d_in, const int* in_sizes, int n_in,
                              void* d_out, int out_size)
{
    const float* spikes = (const float*)d_in[0];   // (T, B, NLAB) fp32
    const float* W1     = (const float*)d_in[1];   // (HID, NLAB)
    const float* W2     = (const float*)d_in[2];   // (SEM, HID)
    float* out = (float*)d_out;                    // [mean1 | mean2]

    __nv_bfloat16 *a1, *spk1, *ws1, *ws2;
    cudaGetSymbolAddress((void**)&a1,   g_a1);
    cudaGetSymbolAddress((void**)&spk1, g_spk1);
    cudaGetSymbolAddress((void**)&ws1,  g_ws1);
    cudaGetSymbolAddress((void**)&ws2,  g_ws2);

    cudaFuncSetAttribute((const void*)gemm_lif<512, true>,
                         cudaFuncAttributeMaxDynamicSharedMemorySize, SMEM_BYTES);
    cudaFuncSetAttribute((const void*)gemm_lif<1024, false>,
                         cudaFuncAttributeMaxDynamicSharedMemorySize, SMEM_BYTES);

    // prep
    f2bf_t_kernel<<<MROWS, 128>>>(spikes, a1);
    wsplit2_both_kernel<<<(HID * NLAB + SEM * HID) / 256, 256>>>(W1, ws1, W2, ws2);

    // layer 1: HMMA 2-split + fused guarded LIF + in-CTA exact fixup
    gemm_lif<512, true><<<dim3(HID / BN2, BATCH), NTHREADS, SMEM_BYTES>>>(
        a1, ws1, W1, spk1, out);

    // layer 2: HMMA 2-split + fused guarded LIF + in-CTA exact fixup (mean only)
    gemm_lif<1024, false><<<dim3(SEM / BN2, BATCH), NTHREADS, SMEM_BYTES>>>(
        spk1, ws2, W2, nullptr, out + (size_t)BATCH * HID);
}

// round 15
// speedup vs baseline: 3.8112x; 1.1045x over previous
#include <cuda_runtime.h>
#include <cuda_bf16.h>
#include <cstdint>

#define T_STEPS 128
#define BATCH   512
#define NLAB    512
#define HID     1024
#define SEM     1024
#define MROWS   (T_STEPS*BATCH)    // 65536
#define FIXCAP  (1u<<20)
#define GUARD   5e-5f

typedef unsigned long long ull;

// ---------------- scratch (device globals; no allocs allowed) ----------------
__device__ __nv_bfloat16 g_a1  [(size_t)MROWS * NLAB];   //  64 MB spikes bf16 (b,t)-major
__device__ __nv_bfloat16 g_spk1[(size_t)MROWS * HID];    // 128 MB layer-1 spikes bf16
__device__ __nv_bfloat16 g_ws1 [2ull * HID * NLAB];      //   2 MB W1 2-splits
__device__ __nv_bfloat16 g_ws2 [2ull * SEM * HID];       //   4 MB W2 2-splits
__device__ unsigned int  g_fixcnt1, g_fixcnt2;
__device__ unsigned int  g_fixlist1[FIXCAP];
__device__ unsigned int  g_fixlist2[FIXCAP];

// ============================================================================
// HMMA 2-split GEMM, BM=128 x BN=256, BK=64, 256 threads (8 warps, 2m x 4n;
// each warp 64m x 64n -> 96 B LDS per MMA), 2-stage cp.async pipeline,
// fused guarded LIF epilogue.
// ============================================================================
#define BM2 128
#define BN2 256
#define BK2 64
#define NTHREADS 256
#define ROWB 144                       // 64 bf16 = 128B + 16B pad (ldsm clean)
#define A_BYTES  (BM2 * ROWB)          // 18432
#define B_SPLIT  (BN2 * ROWB)          // 36864
#define STAGE_BYTES (A_BYTES + 2 * B_SPLIT)   // 92160
#define SMEM_BYTES  (2 * STAGE_BYTES)         // 184320 (>= LIF staging 132096)
#define PITCH 129

__device__ __forceinline__ uint32_t s2u(const void* p) {
    uint32_t a;
    asm("{ .reg .u64 t; cvta.to.shared.u64 t, %1; cvt.u32.u64 %0, t; }" : "=r"(a) : "l"(p));
    return a;
}
__device__ __forceinline__ void cpa16(uint32_t dst, const void* src) {
    asm volatile("cp.async.cg.shared.global [%0], [%1], 16;" :: "r"(dst), "l"(src) : "memory");
}
__device__ __forceinline__ void ldsm_x4(uint32_t* r, uint32_t addr) {
    asm volatile("ldmatrix.sync.aligned.m8n8.x4.shared.b16 {%0,%1,%2,%3}, [%4];"
                 : "=r"(r[0]), "=r"(r[1]), "=r"(r[2]), "=r"(r[3]) : "r"(addr));
}
__device__ __forceinline__ void mma16816(float* c, const uint32_t* a, uint32_t b0, uint32_t b1) {
    asm volatile("mma.sync.aligned.m16n8k16.row.col.f32.bf16.bf16.f32 "
                 "{%0,%1,%2,%3}, {%4,%5,%6,%7}, {%8,%9}, {%0,%1,%2,%3};"
                 : "+f"(c[0]), "+f"(c[1]), "+f"(c[2]), "+f"(c[3])
                 : "r"(a[0]), "r"(a[1]), "r"(a[2]), "r"(a[3]), "r"(b0), "r"(b1));
}

// A rows are (b*128+t); blockIdx.y = b. Epilogue: acc -> smem [u][t] -> LIF.
// Both layers guard-flag borderline elements; WRITE_SPK also emits bf16 spikes.
template <int K, bool WRITE_SPK>
__global__ void __launch_bounds__(NTHREADS, 1)
gemm_lif(const __nv_bfloat16* __restrict__ A,
         const __nv_bfloat16* __restrict__ W,    // [2][1024][K]
         __nv_bfloat16* __restrict__ spk,        // WRITE_SPK only
         float* __restrict__ mean_out,
         unsigned int* __restrict__ fixcnt,
         unsigned int* __restrict__ fixlist)
{
    extern __shared__ char smem[];
    const uint32_t sb = s2u(smem);
    const int tid = threadIdx.x;
    const int b = blockIdx.y;
    const size_t mBase = (size_t)b * BM2;
    const size_t nBase = (size_t)blockIdx.x * BN2;
    constexpr int NC = K / BK2;

    auto load_stage = [&](int chunk, int stage) {
        const uint32_t s0 = sb + stage * STAGE_BYTES;
        const int k0 = chunk * BK2;
        // A: 128 rows x 128B (8 x 16B) = 1024 chunks, 4 per thread
        {
            int row = tid >> 1, kc = (tid & 1) * 2;   // 2 adjacent chunks x2 halves
            const char* src = (const char*)(A + (mBase + row) * (size_t)K + k0);
            cpa16(s0 + row * ROWB + kc * 16,      src + kc * 16);
            cpa16(s0 + row * ROWB + kc * 16 + 16, src + kc * 16 + 16);
            cpa16(s0 + row * ROWB + kc * 16 + 64, src + kc * 16 + 64);
            cpa16(s0 + row * ROWB + kc * 16 + 80, src + kc * 16 + 80);
        }
        // B: 2 splits x 256 rows x 8 chunks = 4096, 16 per thread
#pragma unroll
        for (int j = 0; j < 16; ++j) {
            int c = tid + j * NTHREADS;
            int sp = c >> 11, rem = c & 2047;
            int row = rem >> 3, kc = rem & 7;
            cpa16(s0 + A_BYTES + sp * B_SPLIT + row * ROWB + kc * 16,
                  (const char*)(W + sp * (size_t)1024 * K + (nBase + row) * (size_t)K + k0) + kc * 16);
        }
        asm volatile("cp.async.commit_group;" ::: "memory");
    };

    const int wid  = tid >> 5, lane = tid & 31;
    const int wm = (wid >> 2) * 64;       // 0 / 64
    const int wn = (wid & 3) * 64;        // 0/64/128/192

    float acc[4][8][4];
#pragma unroll
    for (int mi = 0; mi < 4; ++mi)
#pragma unroll
        for (int ni = 0; ni < 8; ++ni)
#pragma unroll
            for (int q = 0; q < 4; ++q) acc[mi][ni][q] = 0.f;

    load_stage(0, 0);

    const uint32_t a_lrow = (uint32_t)(lane & 15);
    const uint32_t a_koff = (uint32_t)(lane >> 4) * 8;
    const uint32_t b_lrow = (uint32_t)(((lane >> 3) & 1) * 8 + (lane & 7));
    const uint32_t b_koff = (uint32_t)(lane >> 4) * 8;

    for (int i = 0; i < NC; ++i) {
        asm volatile("cp.async.wait_group 0;" ::: "memory");
        __syncthreads();                  // stage i visible; all done with i-1
        if (i + 1 < NC) load_stage(i + 1, (i + 1) & 1);   // overlaps compute

        const uint32_t s0 = sb + (i & 1) * STAGE_BYTES;
#pragma unroll
        for (int ks = 0; ks < 4; ++ks) {
            const int k = ks * 16;
            uint32_t af[4][4];
#pragma unroll
            for (int mi = 0; mi < 4; ++mi)
                ldsm_x4(af[mi], s0 + (wm + mi * 16 + a_lrow) * ROWB + (k + a_koff) * 2);
#pragma unroll
            for (int sp = 0; sp < 2; ++sp) {
                const uint32_t bbase = s0 + A_BYTES + sp * B_SPLIT;
#pragma unroll
                for (int nb = 0; nb < 4; ++nb) {
                    uint32_t q[4];
                    ldsm_x4(q, bbase + (wn + nb * 16 + b_lrow) * ROWB + (k + b_koff) * 2);
#pragma unroll
                    for (int mi = 0; mi < 4; ++mi) {
                        mma16816(acc[mi][2 * nb],     af[mi], q[0], q[2]);
                        mma16816(acc[mi][2 * nb + 1], af[mi], q[1], q[3]);
                    }
                }
            }
        }
    }

    // ---- fused guarded LIF epilogue ----
    asm volatile("cp.async.wait_group 0;" ::: "memory");
    __syncthreads();                    // all compute + loads done; reuse smem
    float* sf = (float*)smem;           // [u][t], pitch PITCH (conflict-free)
    const int r0 = lane >> 2, c0 = (lane & 3) * 2;
#pragma unroll
    for (int mi = 0; mi < 4; ++mi)
#pragma unroll
        for (int ni = 0; ni < 8; ++ni) {
            const int t0 = wm + mi * 16 + r0;
            const int u0 = wn + ni * 8 + c0;
            sf[(u0    ) * PITCH + t0    ] = acc[mi][ni][0];
            sf[(u0 + 1) * PITCH + t0    ] = acc[mi][ni][1];
            sf[(u0    ) * PITCH + t0 + 8] = acc[mi][ni][2];
            sf[(u0 + 1) * PITCH + t0 + 8] = acc[mi][ni][3];
        }
    __syncthreads();

    {
        const int u = tid;              // all 256 threads, one unit each
        const size_t uglob = nBase + u;
        float v = 0.f, cnt = 0.f;
        int bad = 0;
#pragma unroll 8
        for (int t = 0; t < T_STEPS; ++t) {
            float x = sf[u * PITCH + t];
            v = fmaf(0.95f, v, x);
            bad |= (fabsf(v - 1.0f) < GUARD);
            float s = (v > 1.0f) ? 1.0f : 0.0f;
            v *= (1.0f - s);
            cnt += s;
            if (WRITE_SPK)
                spk[(mBase + t) * 1024 + uglob] = __float2bfloat16(s);
        }
        mean_out[(size_t)b * 1024 + uglob] = cnt * (1.0f / 128.0f);
        if (bad) {
            unsigned int pos = atomicAdd(fixcnt, 1u);
            if (pos < FIXCAP) fixlist[pos] = (unsigned int)(b * 1024 + uglob);
        }
    }
}

// ============================================================================
// Exact recompute of flagged elements. One warp per element; lane owns
// timestep t = slot*32+lane, computes I via a PRIVATE ASCENDING-k fp32 FMA
// chain (bit-compatible with the R1-validated exact path). LIF via shuffle.
// ============================================================================
template <int KK, bool WRITE_SPK>
__global__ void __launch_bounds__(128)
fix_kernel(const __nv_bfloat16* __restrict__ Ain,  // (b*128+t, KK) bf16 inputs
           const float* __restrict__ Wf,           // (1024, KK) fp32 weights
           __nv_bfloat16* __restrict__ spk,        // layer-1 spike rewrite
           float* __restrict__ mean_out,
           const unsigned int* __restrict__ fixcnt,
           const unsigned int* __restrict__ fixlist)
{
    const unsigned int nfix = min(*fixcnt, FIXCAP);
    const int lane = threadIdx.x & 31;
    const int gw = (blockIdx.x * blockDim.x + threadIdx.x) >> 5;
    const int nw = (gridDim.x * blockDim.x) >> 5;

    for (unsigned int w = gw; w < nfix; w += nw) {
        const unsigned int idx = fixlist[w];
        const int b = idx >> 10, u = idx & 1023;
        const float* wr = Wf + (size_t)u * KK;   // lane-uniform -> broadcast

        float Iv[4];
#pragma unroll
        for (int slot = 0; slot < 4; ++slot) {
            const int t = slot * 32 + lane;
            const __nv_bfloat16* xr = Ain + ((size_t)b * T_STEPS + t) * KK;
            float a = 0.f;
            for (int kk = 0; kk < KK; kk += 8) {        // ascending k, in order
                uint4 raw = *(const uint4*)(xr + kk);   // 8 bf16
                float4 w0 = *(const float4*)(wr + kk);
                float4 w1 = *(const float4*)(wr + kk + 4);
                const __nv_bfloat162* px = (const __nv_bfloat162*)&raw;
                a = fmaf(__bfloat162float(px[0].x), w0.x, a);
                a = fmaf(__bfloat162float(px[0].y), w0.y, a);
                a = fmaf(__bfloat162float(px[1].x), w0.z, a);
                a = fmaf(__bfloat162float(px[1].y), w0.w, a);
                a = fmaf(__bfloat162float(px[2].x), w1.x, a);
                a = fmaf(__bfloat162float(px[2].y), w1.y, a);
                a = fmaf(__bfloat162float(px[3].x), w1.z, a);
                a = fmaf(__bfloat162float(px[3].y), w1.w, a);
            }
            Iv[slot] = a;
        }
        float v = 0.f, cnt = 0.f;
        for (int t = 0; t < T_STEPS; ++t) {
            float x = __shfl_sync(0xffffffffu, Iv[t >> 5], t & 31);
            v = fmaf(0.95f, v, x);
            float s = (v > 1.0f) ? 1.0f : 0.0f;
            v *= (1.0f - s);
            cnt += s;
            if (WRITE_SPK && lane == 0)
                spk[((size_t)b * T_STEPS + t) * 1024 + u] = __float2bfloat16(s);
        }
        if (lane == 0) mean_out[idx] = cnt * (1.0f / 128.0f);
    }
}

// ============================================================================
// prep kernels
// ============================================================================
__global__ void zero_cnt_kernel()
{
    if (threadIdx.x == 0) { g_fixcnt1 = 0; g_fixcnt2 = 0; }
}

// transpose (t,b) -> (b,t) rows while converting fp32 -> bf16 (binary: exact)
__global__ void __launch_bounds__(128)
f2bf_t_kernel(const float* __restrict__ x, __nv_bfloat16* __restrict__ y)
{
    const int row = blockIdx.x;            // t*BATCH + b
    const int t = row >> 9, b = row & 511;
    const float4* src = (const float4*)(x + (size_t)row * NLAB);
    __nv_bfloat16* dst = y + ((size_t)b * T_STEPS + t) * NLAB;
    float4 v = src[threadIdx.x];
    __nv_bfloat162 a; a.x = __float2bfloat16(v.x); a.y = __float2bfloat16(v.y);
    __nv_bfloat162 c; c.x = __float2bfloat16(v.z); c.y = __float2bfloat16(v.w);
    *(__nv_bfloat162*)(dst + threadIdx.x * 4)     = a;
    *(__nv_bfloat162*)(dst + threadIdx.x * 4 + 2) = c;
}

// 2-way bf16 split for BOTH weight matrices in one launch.
// hi = bf16(w), lo = bf16(w - hi); residual ~2^-18 |w|
__global__ void __launch_bounds__(256)
wsplit2_both_kernel(const float* __restrict__ w1, __nv_bfloat16* __restrict__ o1,
                    const float* __restrict__ w2, __nv_bfloat16* __restrict__ o2)
{
    int i = blockIdx.x * blockDim.x + threadIdx.x;
    const int n1 = HID * NLAB;             // 524288
    const int n2 = SEM * HID;              // 1048576
    if (i < n1) {
        float x = w1[i];
        __nv_bfloat16 h = __float2bfloat16(x);
        o1[i] = h; o1[n1 + i] = __float2bfloat16(x - __bfloat162float(h));
    }
    i -= n1;
    if (i >= 0 && i < n2) {
        float x = w2[i];
        __nv_bfloat16 h = __float2bfloat16(x);
        o2[i] = h; o2[n2 + i] = __float2bfloat16(x - __bfloat162float(h));
    }
}

// ---------------------------------------------------------------------------
extern "C" void kernel_launch(void* const* d_in, const int* in_sizes, int n_in,
                              void* d_out, int out_size)
{
    const float* spikes = (const float*)d_in[0];   // (T, B, NLAB) fp32
    const float* W1     = (const float*)d_in[1];   // (HID, NLAB)
    const float* W2     = (const float*)d_in[2];   // (SEM, HID)
    float* out = (float*)d_out;                    // [mean1 | mean2]

    __nv_bfloat16 *a1, *spk1, *ws1, *ws2;
    unsigned int *fc1, *fc2, *fl1, *fl2;
    cudaGetSymbolAddress((void**)&a1,   g_a1);
    cudaGetSymbolAddress((void**)&spk1, g_spk1);
    cudaGetSymbolAddress((void**)&ws1,  g_ws1);
    cudaGetSymbolAddress((void**)&ws2,  g_ws2);
    cudaGetSymbolAddress((void**)&fc1,  g_fixcnt1);
    cudaGetSymbolAddress((void**)&fc2,  g_fixcnt2);
    cudaGetSymbolAddress((void**)&fl1,  g_fixlist1);
    cudaGetSymbolAddress((void**)&fl2,  g_fixlist2);

    cudaFuncSetAttribute((const void*)gemm_lif<512, true>,
                         cudaFuncAttributeMaxDynamicSharedMemorySize, SMEM_BYTES);
    cudaFuncSetAttribute((const void*)gemm_lif<1024, false>,
                         cudaFuncAttributeMaxDynamicSharedMemorySize, SMEM_BYTES);

    // prep
    zero_cnt_kernel<<<1, 32>>>();
    f2bf_t_kernel<<<MROWS, 128>>>(spikes, a1);
    wsplit2_both_kernel<<<(HID * NLAB + SEM * HID) / 256, 256>>>(W1, ws1, W2, ws2);

    // layer 1: HMMA 2-split + fused guarded LIF, then exact-order fixup
    gemm_lif<512, true><<<dim3(HID / BN2, BATCH), NTHREADS, SMEM_BYTES>>>(
        a1, ws1, spk1, out, fc1, fl1);
    fix_kernel<512, true><<<1024, 128>>>(a1, W1, spk1, out, fc1, fl1);

    // layer 2: HMMA 2-split + fused guarded LIF, then exact-order fixup (mean only)
    gemm_lif<1024, false><<<dim3(SEM / BN2, BATCH), NTHREADS, SMEM_BYTES>>>(
        spk1, ws2, nullptr, out + (size_t)BATCH * HID, fc2, fl2);
    fix_kernel<1024, false><<<1024, 128>>>(spk1, W2, nullptr,
                                           out + (size_t)BATCH * HID, fc2, fl2);
}

// round 16
// speedup vs baseline: 3.8316x; 1.0053x over previous
#include <cuda_runtime.h>
#include <cuda_bf16.h>
#include <cstdint>

#define T_STEPS 128
#define BATCH   512
#define NLAB    512
#define HID     1024
#define SEM     1024
#define MROWS   (T_STEPS*BATCH)    // 65536
#define FIXCAP  (1u<<20)
#define GUARD   5e-5f

typedef unsigned long long ull;

// ---------------- scratch (device globals; no allocs allowed) ----------------
// M index is b*128 + t (batch-major): one 128-row GEMM tile = full time
// trajectory of one batch row -> LIF fuses into the epilogue.
__device__ __nv_bfloat16 g_a1  [(size_t)MROWS * NLAB];   //  64 MB spikes bf16 (b,t)-major
__device__ __nv_bfloat16 g_spk1[(size_t)MROWS * HID];    // 128 MB layer-1 spikes bf16
__device__ __nv_bfloat16 g_ws1 [2ull * HID * NLAB];      //   2 MB W1 2-splits
__device__ __nv_bfloat16 g_ws2 [2ull * SEM * HID];       //   4 MB W2 2-splits
__device__ unsigned int  g_fixcnt1, g_fixcnt2;
__device__ unsigned int  g_fixlist1[FIXCAP];
__device__ unsigned int  g_fixlist2[FIXCAP];

// ============================================================================
// HMMA 2-split GEMM, BM=128 x BN=256, BK=64, 512 threads (16 warps, 2m x 8n;
// each warp 64m x 32n -> 128 B LDS per MMA), 2-stage cp.async pipeline,
// fused guarded LIF epilogue with coalesced spike emission.
// ============================================================================
#define BM2 128
#define BN2 256
#define BK2 64
#define NTHREADS 512
#define ROWB 144                       // 64 bf16 = 128B + 16B pad (ldsm clean)
#define A_BYTES  (BM2 * ROWB)          // 18432
#define B_SPLIT  (BN2 * ROWB)          // 36864
#define STAGE_BYTES (A_BYTES + 2 * B_SPLIT)   // 92160
#define SMEM_BYTES  (2 * STAGE_BYTES)         // 184320 (>= LIF staging 132096)
#define PITCH 129

__device__ __forceinline__ uint32_t s2u(const void* p) {
    uint32_t a;
    asm("{ .reg .u64 t; cvta.to.shared.u64 t, %1; cvt.u32.u64 %0, t; }" : "=r"(a) : "l"(p));
    return a;
}
__device__ __forceinline__ void cpa16(uint32_t dst, const void* src) {
    asm volatile("cp.async.cg.shared.global [%0], [%1], 16;" :: "r"(dst), "l"(src) : "memory");
}
__device__ __forceinline__ void ldsm_x4(uint32_t* r, uint32_t addr) {
    asm volatile("ldmatrix.sync.aligned.m8n8.x4.shared.b16 {%0,%1,%2,%3}, [%4];"
                 : "=r"(r[0]), "=r"(r[1]), "=r"(r[2]), "=r"(r[3]) : "r"(addr));
}
__device__ __forceinline__ void mma16816(float* c, const uint32_t* a, uint32_t b0, uint32_t b1) {
    asm volatile("mma.sync.aligned.m16n8k16.row.col.f32.bf16.bf16.f32 "
                 "{%0,%1,%2,%3}, {%4,%5,%6,%7}, {%8,%9}, {%0,%1,%2,%3};"
                 : "+f"(c[0]), "+f"(c[1]), "+f"(c[2]), "+f"(c[3])
                 : "r"(a[0]), "r"(a[1]), "r"(a[2]), "r"(a[3]), "r"(b0), "r"(b1));
}

// A rows are (b*128+t); blockIdx.y = b. Epilogue: acc -> smem [u][t] -> LIF.
// Both layers guard-flag borderline elements; WRITE_SPK also emits bf16 spikes.
template <int K, bool WRITE_SPK>
__global__ void __launch_bounds__(NTHREADS, 1)
gemm_lif(const __nv_bfloat16* __restrict__ A,
         const __nv_bfloat16* __restrict__ W,    // [2][1024][K]
         __nv_bfloat16* __restrict__ spk,        // WRITE_SPK only
         float* __restrict__ mean_out,
         unsigned int* __restrict__ fixcnt,
         unsigned int* __restrict__ fixlist)
{
    extern __shared__ char smem[];
    const uint32_t sb = s2u(smem);
    const int tid = threadIdx.x;
    const int b = blockIdx.y;
    const size_t mBase = (size_t)b * BM2;
    const size_t nBase = (size_t)blockIdx.x * BN2;
    constexpr int NC = K / BK2;

    auto load_stage = [&](int chunk, int stage) {
        const uint32_t s0 = sb + stage * STAGE_BYTES;
        const int k0 = chunk * BK2;
        // A: 128 rows x 128B (8 x 16B); 2 chunks per thread
        {
            int row = tid >> 2, kc = tid & 3;
            const char* src = (const char*)(A + (mBase + row) * (size_t)K + k0);
            cpa16(s0 + row * ROWB + kc * 16,      src + kc * 16);
            cpa16(s0 + row * ROWB + kc * 16 + 64, src + kc * 16 + 64);
        }
        // B: 2 splits x 256 rows x 8 chunks = 4096, 8 per thread
#pragma unroll
        for (int j = 0; j < 8; ++j) {
            int c = tid + j * NTHREADS;
            int sp = c >> 11, rem = c & 2047;
            int row = rem >> 3, kc = rem & 7;
            cpa16(s0 + A_BYTES + sp * B_SPLIT + row * ROWB + kc * 16,
                  (const char*)(W + sp * (size_t)1024 * K + (nBase + row) * (size_t)K + k0) + kc * 16);
        }
        asm volatile("cp.async.commit_group;" ::: "memory");
    };

    const int wid  = tid >> 5, lane = tid & 31;
    const int wm = (wid & 1) * 64;        // 0 / 64         (2 m-warps)
    const int wn = (wid >> 1) * 32;       // 0..224 step 32 (8 n-warps)

    float acc[4][4][4];
#pragma unroll
    for (int mi = 0; mi < 4; ++mi)
#pragma unroll
        for (int ni = 0; ni < 4; ++ni)
#pragma unroll
            for (int q = 0; q < 4; ++q) acc[mi][ni][q] = 0.f;

    load_stage(0, 0);

    const uint32_t a_lrow = (uint32_t)(lane & 15);
    const uint32_t a_koff = (uint32_t)(lane >> 4) * 8;
    const uint32_t b_lrow = (uint32_t)(((lane >> 3) & 1) * 8 + (lane & 7));
    const uint32_t b_koff = (uint32_t)(lane >> 4) * 8;

    for (int i = 0; i < NC; ++i) {
        asm volatile("cp.async.wait_group 0;" ::: "memory");
        __syncthreads();                  // stage i visible; all done with i-1
        if (i + 1 < NC) load_stage(i + 1, (i + 1) & 1);   // overlaps compute

        const uint32_t s0 = sb + (i & 1) * STAGE_BYTES;
#pragma unroll
        for (int ks = 0; ks < 4; ++ks) {
            const int k = ks * 16;
            uint32_t af[4][4];
#pragma unroll
            for (int mi = 0; mi < 4; ++mi)
                ldsm_x4(af[mi], s0 + (wm + mi * 16 + a_lrow) * ROWB + (k + a_koff) * 2);
#pragma unroll
            for (int sp = 0; sp < 2; ++sp) {
                const uint32_t bbase = s0 + A_BYTES + sp * B_SPLIT;
#pragma unroll
                for (int nb = 0; nb < 2; ++nb) {   // 2 x 16n blocks = 32n
                    uint32_t q[4];
                    ldsm_x4(q, bbase + (wn + nb * 16 + b_lrow) * ROWB + (k + b_koff) * 2);
#pragma unroll
                    for (int mi = 0; mi < 4; ++mi) {
                        mma16816(acc[mi][2 * nb],     af[mi], q[0], q[2]);
                        mma16816(acc[mi][2 * nb + 1], af[mi], q[1], q[3]);
                    }
                }
            }
        }
    }

    // ---- fused guarded LIF epilogue ----
    asm volatile("cp.async.wait_group 0;" ::: "memory");
    __syncthreads();                    // all compute + loads done; reuse smem
    float* sf = (float*)smem;           // [u][t], pitch PITCH (conflict-free)
    const int r0 = lane >> 2, c0 = (lane & 3) * 2;
#pragma unroll
    for (int mi = 0; mi < 4; ++mi)
#pragma unroll
        for (int ni = 0; ni < 4; ++ni) {
            const int t0 = wm + mi * 16 + r0;
            const int u0 = wn + ni * 8 + c0;
            sf[(u0    ) * PITCH + t0    ] = acc[mi][ni][0];
            sf[(u0 + 1) * PITCH + t0    ] = acc[mi][ni][1];
            sf[(u0    ) * PITCH + t0 + 8] = acc[mi][ni][2];
            sf[(u0 + 1) * PITCH + t0 + 8] = acc[mi][ni][3];
        }
    __syncthreads();

    if (tid < BN2) {
        const int u = tid;              // one unit per thread
        const size_t uglob = nBase + u;
        float v = 0.f, cnt = 0.f;
        int bad = 0;
#pragma unroll 8
        for (int t = 0; t < T_STEPS; ++t) {
            float x = sf[u * PITCH + t];
            v = fmaf(0.95f, v, x);
            bad |= (fabsf(v - 1.0f) < GUARD);
            float s = (v > 1.0f) ? 1.0f : 0.0f;
            v *= (1.0f - s);
            cnt += s;
            if (WRITE_SPK)
                sf[u * PITCH + t] = s;   // in-place: coalesced emission below
        }
        mean_out[(size_t)b * 1024 + uglob] = cnt * (1.0f / 128.0f);
        if (bad) {
            unsigned int pos = atomicAdd(fixcnt, 1u);
            if (pos < FIXCAP) fixlist[pos] = (unsigned int)(b * 1024 + uglob);
        }
    }

    if (WRITE_SPK) {
        __syncthreads();
        // coalesced transposed emission: each thread packs a (u, u+1) pair
        // for one t -> 4B store; warp covers 64 consecutive u = 128B.
        for (int idx = tid; idx < T_STEPS * (BN2 / 2); idx += NTHREADS) {
            const int t = idx >> 7;             // 0..127
            const int u = (idx & 127) * 2;      // 0..254 even
            __nv_bfloat162 pkt;
            pkt.x = __float2bfloat16(sf[u * PITCH + t]);
            pkt.y = __float2bfloat16(sf[(u + 1) * PITCH + t]);
            *(__nv_bfloat162*)(spk + (mBase + t) * 1024 + nBase + u) = pkt;
        }
    }
}

// ============================================================================
// Exact recompute of flagged elements. One warp per element; lane owns
// timestep t = slot*32+lane, computes I via a PRIVATE ASCENDING-k fp32 FMA
// chain (bit-compatible with the R1-validated exact path). LIF via shuffle.
// ============================================================================
template <int KK, bool WRITE_SPK>
__global__ void __launch_bounds__(128)
fix_kernel(const __nv_bfloat16* __restrict__ Ain,  // (b*128+t, KK) bf16 inputs
           const float* __restrict__ Wf,           // (1024, KK) fp32 weights
           __nv_bfloat16* __restrict__ spk,        // layer-1 spike rewrite
           float* __restrict__ mean_out,
           const unsigned int* __restrict__ fixcnt,
           const unsigned int* __restrict__ fixlist)
{
    const unsigned int nfix = min(*fixcnt, FIXCAP);
    const int lane = threadIdx.x & 31;
    const int gw = (blockIdx.x * blockDim.x + threadIdx.x) >> 5;
    const int nw = (gridDim.x * blockDim.x) >> 5;

    for (unsigned int w = gw; w < nfix; w += nw) {
        const unsigned int idx = fixlist[w];
        const int b = idx >> 10, u = idx & 1023;
        const float* wr = Wf + (size_t)u * KK;   // lane-uniform -> broadcast

        float Iv[4];
#pragma unroll
        for (int slot = 0; slot < 4; ++slot) {
            const int t = slot * 32 + lane;
            const __nv_bfloat16* xr = Ain + ((size_t)b * T_STEPS + t) * KK;
            float a = 0.f;
            for (int kk = 0; kk < KK; kk += 8) {        // ascending k, in order
                uint4 raw = *(const uint4*)(xr + kk);   // 8 bf16
                float4 w0 = *(const float4*)(wr + kk);
                float4 w1 = *(const float4*)(wr + kk + 4);
                const __nv_bfloat162* px = (const __nv_bfloat162*)&raw;
                a = fmaf(__bfloat162float(px[0].x), w0.x, a);
                a = fmaf(__bfloat162float(px[0].y), w0.y, a);
                a = fmaf(__bfloat162float(px[1].x), w0.z, a);
                a = fmaf(__bfloat162float(px[1].y), w0.w, a);
                a = fmaf(__bfloat162float(px[2].x), w1.x, a);
                a = fmaf(__bfloat162float(px[2].y), w1.y, a);
                a = fmaf(__bfloat162float(px[3].x), w1.z, a);
                a = fmaf(__bfloat162float(px[3].y), w1.w, a);
            }
            Iv[slot] = a;
        }
        float v = 0.f, cnt = 0.f;
        for (int t = 0; t < T_STEPS; ++t) {
            float x = __shfl_sync(0xffffffffu, Iv[t >> 5], t & 31);
            v = fmaf(0.95f, v, x);
            float s = (v > 1.0f) ? 1.0f : 0.0f;
            v *= (1.0f - s);
            cnt += s;
            if (WRITE_SPK && lane == 0)
                spk[((size_t)b * T_STEPS + t) * 1024 + u] = __float2bfloat16(s);
        }
        if (lane == 0) mean_out[idx] = cnt * (1.0f / 128.0f);
    }
}

// ============================================================================
// prep kernels
// ============================================================================
__global__ void zero_cnt_kernel()
{
    if (threadIdx.x == 0) { g_fixcnt1 = 0; g_fixcnt2 = 0; }
}

// transpose (t,b) -> (b,t) rows while converting fp32 -> bf16 (binary: exact)
__global__ void __launch_bounds__(128)
f2bf_t_kernel(const float* __restrict__ x, __nv_bfloat16* __restrict__ y)
{
    const int row = blockIdx.x;            // t*BATCH + b
    const int t = row >> 9, b = row & 511;
    const float4* src = (const float4*)(x + (size_t)row * NLAB);
    __nv_bfloat16* dst = y + ((size_t)b * T_STEPS + t) * NLAB;
    float4 v = src[threadIdx.x];
    __nv_bfloat162 a; a.x = __float2bfloat16(v.x); a.y = __float2bfloat16(v.y);
    __nv_bfloat162 c; c.x = __float2bfloat16(v.z); c.y = __float2bfloat16(v.w);
    *(__nv_bfloat162*)(dst + threadIdx.x * 4)     = a;
    *(__nv_bfloat162*)(dst + threadIdx.x * 4 + 2) = c;
}

// 2-way bf16 split for BOTH weight matrices in one launch.
// hi = bf16(w), lo = bf16(w - hi); residual ~2^-18 |w|
__global__ void __launch_bounds__(256)
wsplit2_both_kernel(const float* __restrict__ w1, __nv_bfloat16* __restrict__ o1,
                    const float* __restrict__ w2, __nv_bfloat16* __restrict__ o2)
{
    int i = blockIdx.x * blockDim.x + threadIdx.x;
    const int n1 = HID * NLAB;             // 524288
    const int n2 = SEM * HID;              // 1048576
    if (i < n1) {
        float x = w1[i];
        __nv_bfloat16 h = __float2bfloat16(x);
        o1[i] = h; o1[n1 + i] = __float2bfloat16(x - __bfloat162float(h));
    }
    i -= n1;
    if (i >= 0 && i < n2) {
        float x = w2[i];
        __nv_bfloat16 h = __float2bfloat16(x);
        o2[i] = h; o2[n2 + i] = __float2bfloat16(x - __bfloat162float(h));
    }
}

// ---------------------------------------------------------------------------
extern "C" void kernel_launch(void* const* d_in, const int* in_sizes, int n_in,
                              void* d_out, int out_size)
{
    const float* spikes = (const float*)d_in[0];   // (T, B, NLAB) fp32
    const float* W1     = (const float*)d_in[1];   // (HID, NLAB)
    const float* W2     = (const float*)d_in[2];   // (SEM, HID)
    float* out = (float*)d_out;                    // [mean1 | mean2]

    __nv_bfloat16 *a1, *spk1, *ws1, *ws2;
    unsigned int *fc1, *fc2, *fl1, *fl2;
    cudaGetSymbolAddress((void**)&a1,   g_a1);
    cudaGetSymbolAddress((void**)&spk1, g_spk1);
    cudaGetSymbolAddress((void**)&ws1,  g_ws1);
    cudaGetSymbolAddress((void**)&ws2,  g_ws2);
    cudaGetSymbolAddress((void**)&fc1,  g_fixcnt1);
    cudaGetSymbolAddress((void**)&fc2,  g_fixcnt2);
    cudaGetSymbolAddress((void**)&fl1,  g_fixlist1);
    cudaGetSymbolAddress((void**)&fl2,  g_fixlist2);

    cudaFuncSetAttribute((const void*)gemm_lif<512, true>,
                         cudaFuncAttributeMaxDynamicSharedMemorySize, SMEM_BYTES);
    cudaFuncSetAttribute((const void*)gemm_lif<1024, false>,
                         cudaFuncAttributeMaxDynamicSharedMemorySize, SMEM_BYTES);

    // prep
    zero_cnt_kernel<<<1, 32>>>();
    f2bf_t_kernel<<<MROWS, 128>>>(spikes, a1);
    wsplit2_both_kernel<<<(HID * NLAB + SEM * HID) / 256, 256>>>(W1, ws1, W2, ws2);

    // layer 1: HMMA 2-split + fused guarded LIF, then exact-order fixup
    gemm_lif<512, true><<<dim3(HID / BN2, BATCH), NTHREADS, SMEM_BYTES>>>(
        a1, ws1, spk1, out, fc1, fl1);
    fix_kernel<512, true><<<1024, 128>>>(a1, W1, spk1, out, fc1, fl1);

    // layer 2: HMMA 2-split + fused guarded LIF, then exact-order fixup (mean only)
    gemm_lif<1024, false><<<dim3(SEM / BN2, BATCH), NTHREADS, SMEM_BYTES>>>(
        spk1, ws2, nullptr, out + (size_t)BATCH * HID, fc2, fl2);
    fix_kernel<1024, false><<<1024, 128>>>(spk1, W2, nullptr,
                                           out + (size_t)BATCH * HID, fc2, fl2);
}

// round 17
// speedup vs baseline: 4.0118x; 1.0470x over previous
#include <cuda_runtime.h>
#include <cuda_bf16.h>
#include <cstdint>

#define T_STEPS 128
#define BATCH   512
#define NLAB    512
#define HID     1024
#define SEM     1024
#define MROWS   (T_STEPS*BATCH)    // 65536
#define FIXCAP  (1u<<20)
#define GUARD   5e-5f

typedef unsigned long long ull;

// ---------------- scratch (device globals; no allocs allowed) ----------------
// M index is b*128 + t (batch-major): one 128-row GEMM tile = full time
// trajectory of one batch row -> LIF fuses into the epilogue.
__device__ __nv_bfloat16 g_a1  [(size_t)MROWS * NLAB];   //  64 MB spikes bf16 (b,t)-major
__device__ __nv_bfloat16 g_spk1[(size_t)MROWS * HID];    // 128 MB layer-1 spikes bf16
__device__ __nv_bfloat16 g_ws1 [2ull * HID * NLAB];      //   2 MB W1 2-splits
__device__ __nv_bfloat16 g_ws2 [2ull * SEM * HID];       //   4 MB W2 2-splits
__device__ unsigned int  g_fixcnt1, g_fixcnt2;
__device__ unsigned int  g_fixlist1[FIXCAP];
__device__ unsigned int  g_fixlist2[FIXCAP];

// ============================================================================
// HMMA 2-split GEMM, BM=128 x BN=256 tile, BK=64, 512 threads (16 warps,
// 4m x 4n), 2-stage cp.async pipeline, fused guarded LIF epilogue.
// (R12-validated champion configuration.)
// ============================================================================
#define BM2 128
#define BN2 256
#define BK2 64
#define NTHREADS 512
#define ROWB 144                       // 64 bf16 = 128B + 16B pad (ldsm clean)
#define A_BYTES  (BM2 * ROWB)          // 18432
#define B_SPLIT  (BN2 * ROWB)          // 36864
#define STAGE_BYTES (A_BYTES + 2 * B_SPLIT)   // 92160
#define SMEM_BYTES  (2 * STAGE_BYTES)         // 184320 (>= LIF staging 132096)
#define PITCH 129

__device__ __forceinline__ uint32_t s2u(const void* p) {
    uint32_t a;
    asm("{ .reg .u64 t; cvta.to.shared.u64 t, %1; cvt.u32.u64 %0, t; }" : "=r"(a) : "l"(p));
    return a;
}
__device__ __forceinline__ void cpa16(uint32_t dst, const void* src) {
    asm volatile("cp.async.cg.shared.global [%0], [%1], 16;" :: "r"(dst), "l"(src) : "memory");
}
__device__ __forceinline__ void ldsm_x4(uint32_t* r, uint32_t addr) {
    asm volatile("ldmatrix.sync.aligned.m8n8.x4.shared.b16 {%0,%1,%2,%3}, [%4];"
                 : "=r"(r[0]), "=r"(r[1]), "=r"(r[2]), "=r"(r[3]) : "r"(addr));
}
__device__ __forceinline__ void mma16816(float* c, const uint32_t* a, uint32_t b0, uint32_t b1) {
    asm volatile("mma.sync.aligned.m16n8k16.row.col.f32.bf16.bf16.f32 "
                 "{%0,%1,%2,%3}, {%4,%5,%6,%7}, {%8,%9}, {%0,%1,%2,%3};"
                 : "+f"(c[0]), "+f"(c[1]), "+f"(c[2]), "+f"(c[3])
                 : "r"(a[0]), "r"(a[1]), "r"(a[2]), "r"(a[3]), "r"(b0), "r"(b1));
}

// A rows are (b*128+t); blockIdx.y = b. Epilogue: acc -> smem [u][t] -> LIF.
// Both layers guard-flag borderline elements; WRITE_SPK also emits bf16 spikes.
template <int K, bool WRITE_SPK>
__global__ void __launch_bounds__(NTHREADS, 1)
gemm_lif(const __nv_bfloat16* __restrict__ A,
         const __nv_bfloat16* __restrict__ W,    // [2][1024][K]
         __nv_bfloat16* __restrict__ spk,        // WRITE_SPK only
         float* __restrict__ mean_out,
         unsigned int* __restrict__ fixcnt,
         unsigned int* __restrict__ fixlist)
{
    extern __shared__ char smem[];
    const uint32_t sb = s2u(smem);
    const int tid = threadIdx.x;
    const int b = blockIdx.y;
    const size_t mBase = (size_t)b * BM2;
    const size_t nBase = (size_t)blockIdx.x * BN2;
    constexpr int NC = K / BK2;

    auto load_stage = [&](int chunk, int stage) {
        const uint32_t s0 = sb + stage * STAGE_BYTES;
        const int k0 = chunk * BK2;
        // A: 128 rows x 128B (8 x 16B); 2 chunks per thread
        {
            int row = tid >> 2, kc = tid & 3;
            const char* src = (const char*)(A + (mBase + row) * (size_t)K + k0);
            cpa16(s0 + row * ROWB + kc * 16,      src + kc * 16);
            cpa16(s0 + row * ROWB + kc * 16 + 64, src + kc * 16 + 64);
        }
        // B: 2 splits x 256 rows x 8 chunks = 4096, 8 per thread
#pragma unroll
        for (int j = 0; j < 8; ++j) {
            int c = tid + j * NTHREADS;
            int sp = c >> 11, rem = c & 2047;
            int row = rem >> 3, kc = rem & 7;
            cpa16(s0 + A_BYTES + sp * B_SPLIT + row * ROWB + kc * 16,
                  (const char*)(W + sp * (size_t)1024 * K + (nBase + row) * (size_t)K + k0) + kc * 16);
        }
        asm volatile("cp.async.commit_group;" ::: "memory");
    };

    const int wid  = tid >> 5, lane = tid & 31;
    const int wm = (wid >> 2) * 32;       // 0/32/64/96
    const int wn = (wid & 3) * 64;        // 0/64/128/192

    float acc[2][8][4];
#pragma unroll
    for (int mi = 0; mi < 2; ++mi)
#pragma unroll
        for (int ni = 0; ni < 8; ++ni)
#pragma unroll
            for (int q = 0; q < 4; ++q) acc[mi][ni][q] = 0.f;

    load_stage(0, 0);

    const uint32_t a_lrow = (uint32_t)(lane & 15);
    const uint32_t a_koff = (uint32_t)(lane >> 4) * 8;
    const uint32_t b_lrow = (uint32_t)(((lane >> 3) & 1) * 8 + (lane & 7));
    const uint32_t b_koff = (uint32_t)(lane >> 4) * 8;

    for (int i = 0; i < NC; ++i) {
        asm volatile("cp.async.wait_group 0;" ::: "memory");
        __syncthreads();                  // stage i visible; all done with i-1
        if (i + 1 < NC) load_stage(i + 1, (i + 1) & 1);   // overlaps compute

        const uint32_t s0 = sb + (i & 1) * STAGE_BYTES;
#pragma unroll
        for (int ks = 0; ks < 4; ++ks) {
            const int k = ks * 16;
            uint32_t af[2][4];
#pragma unroll
            for (int mi = 0; mi < 2; ++mi)
                ldsm_x4(af[mi], s0 + (wm + mi * 16 + a_lrow) * ROWB + (k + a_koff) * 2);
#pragma unroll
            for (int sp = 0; sp < 2; ++sp) {
                const uint32_t bbase = s0 + A_BYTES + sp * B_SPLIT;
#pragma unroll
                for (int nb = 0; nb < 4; ++nb) {
                    uint32_t q[4];
                    ldsm_x4(q, bbase + (wn + nb * 16 + b_lrow) * ROWB + (k + b_koff) * 2);
#pragma unroll
                    for (int mi = 0; mi < 2; ++mi) {
                        mma16816(acc[mi][2 * nb],     af[mi], q[0], q[2]);
                        mma16816(acc[mi][2 * nb + 1], af[mi], q[1], q[3]);
                    }
                }
            }
        }
    }

    // ---- fused guarded LIF epilogue ----
    asm volatile("cp.async.wait_group 0;" ::: "memory");
    __syncthreads();                    // all compute + loads done; reuse smem
    float* sf = (float*)smem;           // [u][t], pitch PITCH (conflict-free)
    const int r0 = lane >> 2, c0 = (lane & 3) * 2;
#pragma unroll
    for (int mi = 0; mi < 2; ++mi)
#pragma unroll
        for (int ni = 0; ni < 8; ++ni) {
            const int t0 = wm + mi * 16 + r0;
            const int u0 = wn + ni * 8 + c0;
            sf[(u0    ) * PITCH + t0    ] = acc[mi][ni][0];
            sf[(u0 + 1) * PITCH + t0    ] = acc[mi][ni][1];
            sf[(u0    ) * PITCH + t0 + 8] = acc[mi][ni][2];
            sf[(u0 + 1) * PITCH + t0 + 8] = acc[mi][ni][3];
        }
    __syncthreads();

    if (tid < BN2) {
        const int u = tid;              // one unit per thread
        const size_t uglob = nBase + u;
        float v = 0.f, cnt = 0.f;
        int bad = 0;
#pragma unroll 8
        for (int t = 0; t < T_STEPS; ++t) {
            float x = sf[u * PITCH + t];
            v = fmaf(0.95f, v, x);
            bad |= (fabsf(v - 1.0f) < GUARD);
            float s = (v > 1.0f) ? 1.0f : 0.0f;
            v *= (1.0f - s);
            cnt += s;
            if (WRITE_SPK)
                spk[(mBase + t) * 1024 + uglob] = __float2bfloat16(s);
        }
        mean_out[(size_t)b * 1024 + uglob] = cnt * (1.0f / 128.0f);
        if (bad) {
            unsigned int pos = atomicAdd(fixcnt, 1u);
            if (pos < FIXCAP) fixlist[pos] = (unsigned int)(b * 1024 + uglob);
        }
    }
}

// ============================================================================
// Exact recompute of flagged elements. One warp per element; lane owns
// timestep t = slot*32+lane, computes I via a PRIVATE ASCENDING-k fp32 FMA
// chain (bit-compatible with the R1-validated exact path). LIF via shuffle.
// ============================================================================
template <int KK, bool WRITE_SPK>
__global__ void __launch_bounds__(128)
fix_kernel(const __nv_bfloat16* __restrict__ Ain,  // (b*128+t, KK) bf16 inputs
           const float* __restrict__ Wf,           // (1024, KK) fp32 weights
           __nv_bfloat16* __restrict__ spk,        // layer-1 spike rewrite
           float* __restrict__ mean_out,
           const unsigned int* __restrict__ fixcnt,
           const unsigned int* __restrict__ fixlist)
{
    const unsigned int nfix = min(*fixcnt, FIXCAP);
    const int lane = threadIdx.x & 31;
    const int gw = (blockIdx.x * blockDim.x + threadIdx.x) >> 5;
    const int nw = (gridDim.x * blockDim.x) >> 5;

    for (unsigned int w = gw; w < nfix; w += nw) {
        const unsigned int idx = fixlist[w];
        const int b = idx >> 10, u = idx & 1023;
        const float* wr = Wf + (size_t)u * KK;   // lane-uniform -> broadcast

        float Iv[4];
#pragma unroll
        for (int slot = 0; slot < 4; ++slot) {
            const int t = slot * 32 + lane;
            const __nv_bfloat16* xr = Ain + ((size_t)b * T_STEPS + t) * KK;
            float a = 0.f;
            for (int kk = 0; kk < KK; kk += 8) {        // ascending k, in order
                uint4 raw = *(const uint4*)(xr + kk);   // 8 bf16
                float4 w0 = *(const float4*)(wr + kk);
                float4 w1 = *(const float4*)(wr + kk + 4);
                const __nv_bfloat162* px = (const __nv_bfloat162*)&raw;
                a = fmaf(__bfloat162float(px[0].x), w0.x, a);
                a = fmaf(__bfloat162float(px[0].y), w0.y, a);
                a = fmaf(__bfloat162float(px[1].x), w0.z, a);
                a = fmaf(__bfloat162float(px[1].y), w0.w, a);
                a = fmaf(__bfloat162float(px[2].x), w1.x, a);
                a = fmaf(__bfloat162float(px[2].y), w1.y, a);
                a = fmaf(__bfloat162float(px[3].x), w1.z, a);
                a = fmaf(__bfloat162float(px[3].y), w1.w, a);
            }
            Iv[slot] = a;
        }
        float v = 0.f, cnt = 0.f;
        for (int t = 0; t < T_STEPS; ++t) {
            float x = __shfl_sync(0xffffffffu, Iv[t >> 5], t & 31);
            v = fmaf(0.95f, v, x);
            float s = (v > 1.0f) ? 1.0f : 0.0f;
            v *= (1.0f - s);
            cnt += s;
            if (WRITE_SPK && lane == 0)
                spk[((size_t)b * T_STEPS + t) * 1024 + u] = __float2bfloat16(s);
        }
        if (lane == 0) mean_out[idx] = cnt * (1.0f / 128.0f);
    }
}

// ============================================================================
// prep kernels
// ============================================================================
// transpose (t,b) -> (b,t) rows while converting fp32 -> bf16 (binary: exact)
__global__ void __launch_bounds__(128)
f2bf_t_kernel(const float* __restrict__ x, __nv_bfloat16* __restrict__ y)
{
    const int row = blockIdx.x;            // t*BATCH + b
    const int t = row >> 9, b = row & 511;
    const float4* src = (const float4*)(x + (size_t)row * NLAB);
    __nv_bfloat16* dst = y + ((size_t)b * T_STEPS + t) * NLAB;
    float4 v = src[threadIdx.x];
    __nv_bfloat162 a; a.x = __float2bfloat16(v.x); a.y = __float2bfloat16(v.y);
    __nv_bfloat162 c; c.x = __float2bfloat16(v.z); c.y = __float2bfloat16(v.w);
    *(__nv_bfloat162*)(dst + threadIdx.x * 4)     = a;
    *(__nv_bfloat162*)(dst + threadIdx.x * 4 + 2) = c;
}

// 2-way bf16 split for BOTH weight matrices in one launch; also resets the
// fix counters (block 0 thread 0 — kernel completes before gemm1 launches).
// hi = bf16(w), lo = bf16(w - hi); residual ~2^-18 |w|
__global__ void __launch_bounds__(256)
wsplit2_both_kernel(const float* __restrict__ w1, __nv_bfloat16* __restrict__ o1,
                    const float* __restrict__ w2, __nv_bfloat16* __restrict__ o2)
{
    if (blockIdx.x == 0 && threadIdx.x == 0) { g_fixcnt1 = 0; g_fixcnt2 = 0; }
    int i = blockIdx.x * blockDim.x + threadIdx.x;
    const int n1 = HID * NLAB;             // 524288
    const int n2 = SEM * HID;              // 1048576
    if (i < n1) {
        float x = w1[i];
        __nv_bfloat16 h = __float2bfloat16(x);
        o1[i] = h; o1[n1 + i] = __float2bfloat16(x - __bfloat162float(h));
    }
    i -= n1;
    if (i >= 0 && i < n2) {
        float x = w2[i];
        __nv_bfloat16 h = __float2bfloat16(x);
        o2[i] = h; o2[n2 + i] = __float2bfloat16(x - __bfloat162float(h));
    }
}

// ---------------------------------------------------------------------------
extern "C" void kernel_launch(void* const* d_in, const int* in_sizes, int n_in,
                              void* d_out, int out_size)
{
    const float* spikes = (const float*)d_in[0];   // (T, B, NLAB) fp32
    const float* W1     = (const float*)d_in[1];   // (HID, NLAB)
    const float* W2     = (const float*)d_in[2];   // (SEM, HID)
    float* out = (float*)d_out;                    // [mean1 | mean2]

    __nv_bfloat16 *a1, *spk1, *ws1, *ws2;
    unsigned int *fc1, *fc2, *fl1, *fl2;
    cudaGetSymbolAddress((void**)&a1,   g_a1);
    cudaGetSymbolAddress((void**)&spk1, g_spk1);
    cudaGetSymbolAddress((void**)&ws1,  g_ws1);
    cudaGetSymbolAddress((void**)&ws2,  g_ws2);
    cudaGetSymbolAddress((void**)&fc1,  g_fixcnt1);
    cudaGetSymbolAddress((void**)&fc2,  g_fixcnt2);
    cudaGetSymbolAddress((void**)&fl1,  g_fixlist1);
    cudaGetSymbolAddress((void**)&fl2,  g_fixlist2);

    cudaFuncSetAttribute((const void*)gemm_lif<512, true>,
                         cudaFuncAttributeMaxDynamicSharedMemorySize, SMEM_BYTES);
    cudaFuncSetAttribute((const void*)gemm_lif<1024, false>,
                         cudaFuncAttributeMaxDynamicSharedMemorySize, SMEM_BYTES);

    // prep (wsplit also resets fix counters)
    f2bf_t_kernel<<<MROWS, 128>>>(spikes, a1);
    wsplit2_both_kernel<<<(HID * NLAB + SEM * HID) / 256, 256>>>(W1, ws1, W2, ws2);

    // layer 1: HMMA 2-split + fused guarded LIF, then exact-order fixup
    gemm_lif<512, true><<<dim3(HID / BN2, BATCH), NTHREADS, SMEM_BYTES>>>(
        a1, ws1, spk1, out, fc1, fl1);
    fix_kernel<512, true><<<512, 128>>>(a1, W1, spk1, out, fc1, fl1);

    // layer 2: HMMA 2-split + fused guarded LIF, then exact-order fixup (mean only)
    gemm_lif<1024, false><<<dim3(SEM / BN2, BATCH), NTHREADS, SMEM_BYTES>>>(
        spk1, ws2, nullptr, out + (size_t)BATCH * HID, fc2, fl2);
    fix_kernel<1024, false><<<512, 128>>>(spk1, W2, nullptr,
                                          out + (size_t)BATCH * HID, fc2, fl2);
}